// round 15
// baseline (speedup 1.0000x reference)
#include <cuda_runtime.h>
#include <cuda_fp16.h>
#include <cstdint>

#define BB 4
#define C 256
#define H 64
#define W 64
#define HW 4096
#define G 32
#define KK 9
#define OC_OFF 18
#define CK 2304  /* C * KK */
#define NCHUNK 36 /* CK / 64 */

// ---------------- device scratch (static, no runtime allocation) -------------
__device__ float g_offset[BB * OC_OFF * HW];                        // 1.18 MB
// A blocks: [b][ptile 32][chunk 36] of 16 KB (128 pixels x 128 B, swizzled)
__device__ __align__(16) char g_val2[(size_t)BB * 32 * NCHUNK * 16384];  // 75.5 MB
// B blocks: [stage][chunk 36] of 32 KB (256 oc x 128 B, swizzled)
__device__ __align__(16) char g_wb[2 * NCHUNK * 32768];             // 2.36 MB
__device__ float g_tmp[(size_t)BB * C * HW];                        // 16.8 MB
__device__ float g_act[(size_t)BB * C * HW];                        // 16.8 MB
__device__ float g_stat[BB * G * 2];                                // group sums

// ---------------- helpers ----------------------------------------------------
__device__ __forceinline__ uint32_t smem_u32(const void* p) {
    uint32_t a;
    asm("{ .reg .u64 t; cvta.to.shared.u64 t, %1; cvt.u32.u64 %0, t; }"
        : "=r"(a) : "l"(p));
    return a;
}
__device__ __forceinline__ uint32_t swz(uint32_t o) { return o ^ ((o >> 3) & 0x70); }

__device__ __forceinline__ void bulk_cp(uint32_t sdst, const void* gsrc,
                                        uint32_t bytes, uint32_t mbar) {
    asm volatile(
        "cp.async.bulk.shared::cluster.global.mbarrier::complete_tx::bytes "
        "[%0], [%1], %2, [%3];"
        :: "r"(sdst), "l"(gsrc), "r"(bytes), "r"(mbar) : "memory");
}
__device__ __forceinline__ void mbar_init(uint32_t a, uint32_t cnt) {
    asm volatile("mbarrier.init.shared.b64 [%0], %1;" :: "r"(a), "r"(cnt) : "memory");
}
__device__ __forceinline__ void mbar_expect(uint32_t a, uint32_t bytes) {
    asm volatile("mbarrier.arrive.expect_tx.shared.b64 _, [%0], %1;"
                 :: "r"(a), "r"(bytes) : "memory");
}
__device__ __forceinline__ void mbar_arrive_rel(uint32_t a) {
    asm volatile("mbarrier.arrive.release.cta.shared::cta.b64 _, [%0];"
                 :: "r"(a) : "memory");
}
__device__ __forceinline__ void mbar_wait(uint32_t a, uint32_t parity) {
    asm volatile(
        "{\n\t.reg .pred P1;\n\t"
        "WL%=:\n\t"
        "mbarrier.try_wait.parity.acquire.cta.shared::cta.b64 P1, [%0], %1, 0x989680;\n\t"
        "@P1 bra.uni WD%=;\n\t"
        "bra.uni WL%=;\n\t"
        "WD%=:\n\t}" :: "r"(a), "r"(parity) : "memory");
}

#define MMA_F16(d, a, bfr)                                                   \
    asm volatile(                                                            \
        "mma.sync.aligned.m16n8k16.row.col.f32.f16.f16.f32 "                 \
        "{%0,%1,%2,%3}, {%4,%5,%6,%7}, {%8,%9}, {%0,%1,%2,%3};"              \
        : "+f"((d)[0]), "+f"((d)[1]), "+f"((d)[2]), "+f"((d)[3])             \
        : "r"((a)[0]), "r"((a)[1]), "r"((a)[2]), "r"((a)[3]),                \
          "r"((bfr)[0]), "r"((bfr)[1]))

#define LDSM_X4(fr, addr)                                                    \
    asm volatile("ldmatrix.sync.aligned.m8n8.x4.shared.b16 "                 \
                 "{%0,%1,%2,%3}, [%4];"                                      \
                 : "=r"((fr)[0]), "=r"((fr)[1]), "=r"((fr)[2]), "=r"((fr)[3])\
                 : "r"(addr))

// ---------------- weight reorder (swizzled chunk blocks) + stage-1 init ------
__global__ void wprep_kernel(const float* __restrict__ w1, const float* __restrict__ w2,
                             const float* __restrict__ bias1) {
    int i = blockIdx.x * 256 + threadIdx.x;
    if (blockIdx.x == 0 && threadIdx.x < BB * G * 2) g_stat[threadIdx.x] = 0.f;
    if (i < BB * OC_OFF * HW) {
        int oc = (i / HW) % OC_OFF;
        g_offset[i] = bias1[oc];
    }
    if (i >= 2 * C * CK) return;
    int s = i / (C * CK);
    int rem = i - s * (C * CK);
    int oc = rem / CK;
    int r = rem - oc * CK;
    int k = r >> 8;
    int cin = r & 255;
    const float* w = s ? w2 : w1;
    __half hv = __float2half(w[(size_t)oc * CK + cin * 9 + k]);
    int chunk = r >> 6;
    uint32_t o = (uint32_t)oc * 128 + (uint32_t)(r & 63) * 2;
    *reinterpret_cast<unsigned short*>(
        g_wb + (((size_t)s * NCHUNK + chunk) << 15) + swz(o)) =
        __half_as_ushort(hv);
}

// ---------------- init offset buffer with bias + clear group stats -----------
__global__ void init_offset_kernel(const float* __restrict__ bias) {
    int i = blockIdx.x * 256 + threadIdx.x;
    if (blockIdx.x == 0 && threadIdx.x < BB * G * 2) g_stat[threadIdx.x] = 0.f;
    if (i < BB * OC_OFF * HW) {
        int oc = (i / HW) % OC_OFF;
        g_offset[i] = bias[oc];
    }
}

// ---------------- offset conv3x3: C in -> 18 out, pad 1 ----------------------
#define CIN_CHUNK 64
__global__ __launch_bounds__(256) void offset_conv_kernel(
    const float* __restrict__ xin, const float* __restrict__ woff, int use_internal) {
    __shared__ __align__(16) float ws[CIN_CHUNK * 9 * 20];
    __shared__ float xs[2][18 * 18];

    int tid = threadIdx.x;
    int bz = blockIdx.z;
    int b = bz >> 2;
    int chunk = bz & 3;
    int cin0 = chunk * CIN_CHUNK;

    for (int idx = tid; idx < CIN_CHUNK * 9 * 18; idx += 256) {
        int cl = idx / 162;
        int rem = idx - cl * 162;
        int k = rem / 18;
        int oc = rem - k * 18;
        ws[(cl * 9 + k) * 20 + oc] =
            woff[(size_t)oc * (C * 9) + (size_t)(cin0 + cl) * 9 + k];
    }

    int ty = tid >> 4, tx = tid & 15;
    int py0 = blockIdx.y * 16, px0 = blockIdx.x * 16;

    float acc[18];
#pragma unroll
    for (int i = 0; i < 18; i++) acc[i] = 0.f;

    const float* src = use_internal ? g_act : xin;
    const float* xb = src + ((size_t)b * C + cin0) * HW;

    int hidx0 = tid;
    int hidx1 = tid + 256;
    int hr0 = hidx0 / 18, hc0 = hidx0 - hr0 * 18;
    int hr1 = hidx1 / 18, hc1 = hidx1 - hr1 * 18;
    int gy0 = py0 - 1 + hr0, gx0 = px0 - 1 + hc0;
    int gy1 = py0 - 1 + hr1, gx1 = px0 - 1 + hc1;
    bool v0 = (gy0 >= 0 && gy0 < H && gx0 >= 0 && gx0 < W);
    bool v1 = (hidx1 < 324) && (gy1 >= 0 && gy1 < H && gx1 >= 0 && gx1 < W);
    int go0 = gy0 * W + gx0, go1 = gy1 * W + gx1;

    {
        const float* xc = xb;
        xs[0][hidx0] = v0 ? xc[go0] : 0.f;
        if (hidx1 < 324) xs[0][hidx1] = v1 ? xc[go1] : 0.f;
    }
    __syncthreads();

#pragma unroll 1
    for (int cl = 0; cl < CIN_CHUNK; cl++) {
        int cur = cl & 1;
        if (cl + 1 < CIN_CHUNK) {
            const float* xn = xb + (size_t)(cl + 1) * HW;
            xs[cur ^ 1][hidx0] = v0 ? __ldg(xn + go0) : 0.f;
            if (hidx1 < 324) xs[cur ^ 1][hidx1] = v1 ? __ldg(xn + go1) : 0.f;
        }

        float xv[9];
#pragma unroll
        for (int ky = 0; ky < 3; ky++)
#pragma unroll
            for (int kx = 0; kx < 3; kx++)
                xv[ky * 3 + kx] = xs[cur][(ty + ky) * 18 + (tx + kx)];

#pragma unroll
        for (int k = 0; k < 9; k++) {
            const float* wr = &ws[(cl * 9 + k) * 20];
            float xk = xv[k];
#pragma unroll
            for (int oc = 0; oc < 18; oc++) acc[oc] += xk * wr[oc];
        }
        __syncthreads();
    }

    int p = (py0 + ty) * W + (px0 + tx);
    float* ob = g_offset + (size_t)b * OC_OFF * HW + p;
#pragma unroll
    for (int oc = 0; oc < 18; oc++) atomicAdd(ob + (size_t)oc * HW, acc[oc]);
}

// ---------------- bilinear gather -> swizzled A blocks (fp16) ----------------
__global__ __launch_bounds__(256) void gather_kernel(const float* __restrict__ xin,
                                                     int use_internal) {
    __shared__ __align__(16) char sv[256 * 128];  // 32 KB = 2 ptile blocks
    int tid = threadIdx.x;
    int p = blockIdx.x * 256 + tid;
    int k = blockIdx.y;
    int b = blockIdx.z >> 2;
    int cin0 = (blockIdx.z & 3) * 64;
    int h = p >> 6, w = p & 63;

    const float* off = g_offset + ((size_t)b * OC_OFF + 2 * k) * HW + p;
    float dy = off[0];
    float dx = off[HW];
    int ky = k / 3, kx = k - ky * 3;

    float py = dy + (float)(h - 1 + ky);
    float px = dx + (float)(w - 1 + kx);
    float fy = floorf(py), fx = floorf(px);
    int iy0 = (int)fy, ix0 = (int)fx;
    float ly = py - fy, lx = px - fx;

    float vy0 = (iy0 >= 0 && iy0 < H) ? 1.f : 0.f;
    float vy1 = (iy0 + 1 >= 0 && iy0 + 1 < H) ? 1.f : 0.f;
    float vx0 = (ix0 >= 0 && ix0 < W) ? 1.f : 0.f;
    float vx1 = (ix0 + 1 >= 0 && ix0 + 1 < W) ? 1.f : 0.f;

    float w00 = (1.f - ly) * (1.f - lx) * vy0 * vx0;
    float w01 = (1.f - ly) * lx * vy0 * vx1;
    float w10 = ly * (1.f - lx) * vy1 * vx0;
    float w11 = ly * lx * vy1 * vx1;

    int cy0 = min(max(iy0, 0), H - 1);
    int cy1 = min(max(iy0 + 1, 0), H - 1);
    int cx0 = min(max(ix0, 0), W - 1);
    int cx1 = min(max(ix0 + 1, 0), W - 1);
    int i00 = cy0 * W + cx0, i01 = cy0 * W + cx1;
    int i10 = cy1 * W + cx0, i11 = cy1 * W + cx1;

    const float* src = use_internal ? g_act : xin;
    const float* xb = src + (size_t)b * C * HW;

#pragma unroll 1
    for (int g = 0; g < 4; g++) {
        int c0 = cin0 + g * 16;
        const float* xc = xb + (size_t)c0 * HW;
        float v00[16], v01[16], v10[16], v11[16];
#pragma unroll
        for (int j = 0; j < 16; j++) v00[j] = __ldg(xc + (size_t)j * HW + i00);
#pragma unroll
        for (int j = 0; j < 16; j++) v01[j] = __ldg(xc + (size_t)j * HW + i01);
#pragma unroll
        for (int j = 0; j < 16; j++) v10[j] = __ldg(xc + (size_t)j * HW + i10);
#pragma unroll
        for (int j = 0; j < 16; j++) v11[j] = __ldg(xc + (size_t)j * HW + i11);

        __align__(16) __half hb[16];
#pragma unroll
        for (int j = 0; j < 16; j++) {
            float s = w00 * v00[j] + w01 * v01[j] + w10 * v10[j] + w11 * v11[j];
            hb[j] = __float2half(s);
        }
        uint32_t o0 = (uint32_t)tid * 128 + g * 32;
        uint32_t o1 = o0 + 16;
        *reinterpret_cast<uint4*>(sv + swz(o0)) = *reinterpret_cast<const uint4*>(hb);
        *reinterpret_cast<uint4*>(sv + swz(o1)) =
            *reinterpret_cast<const uint4*>(hb + 8);
    }
    __syncthreads();

    int chunk = k * 4 + (blockIdx.z & 3);
#pragma unroll
    for (int t = 0; t < 8; t++) {
        uint32_t idx = ((uint32_t)tid + t * 256) * 16;
        int pt = blockIdx.x * 2 + (idx >> 14);
        size_t base = (((size_t)b * 32 + pt) * NCHUNK + chunk) << 14;
        *reinterpret_cast<uint4*>(g_val2 + base + (idx & 16383)) =
            *reinterpret_cast<const uint4*>(sv + idx);
    }
}

// ---------------- HMMA GEMM, warp-decoupled bulk-copy pipeline ---------------
// CTA tile 128(pixels) x 256(oc), 512 threads, grid (32, BB). fp16 x fp16,
// fp32 accum. 4-stage pipeline: full[] tx-barriers + empty[] (16 warp arrivals)
// -- NO block-wide sync in the mainloop.
#define NSTG 4
#define STG 49152
#define GSMEM (NSTG * STG) /* 196608 */

__global__ __launch_bounds__(512, 1) void mma_gemm_kernel(int stage) {
    extern __shared__ __align__(16) char smem[];
    __shared__ __align__(8) unsigned long long mbfull8[NSTG], mbempty8[NSTG];
    uint32_t sb = smem_u32(smem);
    uint32_t mf = smem_u32(mbfull8);
    uint32_t me = smem_u32(mbempty8);
    int tid = threadIdx.x;
    int wid = tid >> 5, lane = tid & 31;
    int b = blockIdx.y;
    int ptile = blockIdx.x;
    int p0 = ptile * 128;

    const char* Ag = g_val2 + (((size_t)b * 32 + ptile) * NCHUNK << 14);
    const char* Bg = g_wb + ((size_t)stage * NCHUNK << 15);

    if (tid == 0) {
#pragma unroll
        for (int s = 0; s < NSTG; s++) {
            mbar_init(mf + 8 * s, 1);
            mbar_init(me + 8 * s, 16);
        }
    }
    __syncthreads();

    // prologue: fill stages 0..3
    if (tid == 0) {
#pragma unroll
        for (int s = 0; s < NSTG; s++) {
            mbar_expect(mf + 8 * s, 49152);
            bulk_cp(sb + s * STG, Ag + ((size_t)s << 14), 16384, mf + 8 * s);
            bulk_cp(sb + s * STG + 16384, Bg + ((size_t)s << 15), 32768, mf + 8 * s);
        }
    }

    int mwarp = wid >> 3, nwarp = wid & 7;
    uint32_t arow_off[4];
#pragma unroll
    for (int mt = 0; mt < 4; mt++)
        arow_off[mt] = (uint32_t)(mwarp * 64 + mt * 16 + (lane & 15)) * 128;
    uint32_t acol = (lane >> 4) * 16;
    uint32_t brow_off[2];
#pragma unroll
    for (int ntp = 0; ntp < 2; ntp++)
        brow_off[ntp] =
            (uint32_t)(nwarp * 32 + ntp * 16 + (lane >> 4) * 8 + (lane & 7)) * 128;
    uint32_t bcol = ((lane >> 3) & 1) * 16;

    float acc[4][4][4];
#pragma unroll
    for (int i = 0; i < 4; i++)
#pragma unroll
        for (int j = 0; j < 4; j++)
#pragma unroll
            for (int q = 0; q < 4; q++) acc[i][j][q] = 0.f;

#pragma unroll 1
    for (int i = 0; i < NCHUNK; i++) {
        int buf = i & (NSTG - 1);
        uint32_t ph = (uint32_t)(i >> 2) & 1;
        mbar_wait(mf + 8 * buf, ph);

        uint32_t cb = sb + (uint32_t)buf * STG;
#pragma unroll
        for (int kk = 0; kk < 4; kk++) {
            uint32_t koff = (uint32_t)kk * 32;
            uint32_t ah[4][4], bb[2][4];
#pragma unroll
            for (int mt = 0; mt < 4; mt++)
                LDSM_X4(ah[mt], cb + swz(arow_off[mt] + acol + koff));
#pragma unroll
            for (int ntp = 0; ntp < 2; ntp++)
                LDSM_X4(bb[ntp], cb + 16384 + swz(brow_off[ntp] + bcol + koff));
#pragma unroll
            for (int mt = 0; mt < 4; mt++)
#pragma unroll
                for (int nt = 0; nt < 4; nt++)
                    MMA_F16(acc[mt][nt], ah[mt], &bb[nt >> 1][(nt & 1) * 2]);
        }

        // consumer release: one arrival per warp
        if (lane == 0) mbar_arrive_rel(me + 8 * buf);

        // producer (thread 0): refill this buffer with chunk i+NSTG
        if (tid == 0 && i + NSTG < NCHUNK) {
            int nc = i + NSTG;
            mbar_wait(me + 8 * buf, ph);  // all 16 warps done with round i
            mbar_expect(mf + 8 * buf, 49152);
            bulk_cp(cb, Ag + ((size_t)nc << 14), 16384, mf + 8 * buf);
            bulk_cp(cb + 16384, Bg + ((size_t)nc << 15), 32768, mf + 8 * buf);
        }
    }
    __syncthreads();

    // ---------------- epilogue: two passes of 128 oc via smem transpose ------
    float* sf = reinterpret_cast<float*>(smem);
    int rl = lane >> 2;
    int cl2 = (lane & 3) * 2;
#pragma unroll 1
    for (int q = 0; q < 2; q++) {
        if ((nwarp >> 2) == q) {
#pragma unroll
            for (int mt = 0; mt < 4; mt++) {
#pragma unroll
                for (int nt = 0; nt < 4; nt++) {
                    int m = mwarp * 64 + mt * 16 + rl;
                    int n = (nwarp & 3) * 32 + nt * 8 + cl2;
                    sf[n * 132 + m] = acc[mt][nt][0];
                    sf[(n + 1) * 132 + m] = acc[mt][nt][1];
                    sf[n * 132 + m + 8] = acc[mt][nt][2];
                    sf[(n + 1) * 132 + m + 8] = acc[mt][nt][3];
                }
            }
        }
        __syncthreads();

#pragma unroll
        for (int t = 0; t < 8; t++) {
            int idx = tid + t * 512;
            int n = idx >> 5;
            int ms = (idx & 31) * 4;
            float4 v = *reinterpret_cast<const float4*>(sf + n * 132 + ms);
            int oc = q * 128 + n;
            *reinterpret_cast<float4*>(g_tmp + ((size_t)b * C + oc) * HW + p0 + ms) = v;

            float s1 = v.x + v.y + v.z + v.w;
            float s2 = v.x * v.x + v.y * v.y + v.z * v.z + v.w * v.w;
#pragma unroll
            for (int o = 16; o > 0; o >>= 1) {
                s1 += __shfl_xor_sync(0xffffffffu, s1, o);
                s2 += __shfl_xor_sync(0xffffffffu, s2, o);
            }
            if (lane == 0) {
                int bg = b * G + (oc >> 3);
                atomicAdd(&g_stat[bg * 2], s1);
                atomicAdd(&g_stat[bg * 2 + 1], s2);
            }
        }
        __syncthreads();
    }
}

// ---------------- GroupNorm apply (+ReLU, optional residual) -----------------
__global__ __launch_bounds__(256) void gn_kernel(const float* __restrict__ gamma,
                                                 const float* __restrict__ beta,
                                                 const float* __restrict__ residual,
                                                 float* __restrict__ outp,
                                                 int use_internal) {
    int bg = blockIdx.x;
    int b = bg >> 5;
    int g = bg & 31;
    int quarter = blockIdx.y;
    size_t chan_off = ((size_t)b * C + (size_t)g * 8 + (size_t)quarter * 2) * HW;
    const float4* in4 = reinterpret_cast<const float4*>(g_tmp + chan_off);

    __shared__ float stats[2];
    if (threadIdx.x == 0) {
        float inv_n = 1.f / 32768.f;
        float mu = g_stat[bg * 2] * inv_n;
        stats[0] = mu;
        stats[1] = rsqrtf(g_stat[bg * 2 + 1] * inv_n - mu * mu + 1e-5f);
    }
    __syncthreads();
    float mu = stats[0], rstd = stats[1];

    int tid = threadIdx.x;
    float* dst = (use_internal ? g_act : outp) + chan_off;
    float4* out4 = reinterpret_cast<float4*>(dst);
    const float4* res4 =
        residual ? reinterpret_cast<const float4*>(residual + chan_off) : nullptr;

    for (int i = tid; i < 2 * HW / 4; i += 256) {
        int c = g * 8 + quarter * 2 + (i >> 10);
        float gm = gamma[c] * rstd;
        float bt = beta[c] - mu * gm;
        float4 v = in4[i];
        v.x = v.x * gm + bt;
        v.y = v.y * gm + bt;
        v.z = v.z * gm + bt;
        v.w = v.w * gm + bt;
        if (res4) {
            float4 r = res4[i];
            v.x += r.x; v.y += r.y; v.z += r.z; v.w += r.w;
        }
        v.x = fmaxf(v.x, 0.f);
        v.y = fmaxf(v.y, 0.f);
        v.z = fmaxf(v.z, 0.f);
        v.w = fmaxf(v.w, 0.f);
        out4[i] = v;
    }
}

// ---------------- launcher ---------------------------------------------------
extern "C" void kernel_launch(void* const* d_in, const int* in_sizes, int n_in,
                              void* d_out, int out_size) {
    const float* x      = (const float*)d_in[0];
    const float* w_off1 = (const float*)d_in[1];
    const float* b_off1 = (const float*)d_in[2];
    const float* w_off2 = (const float*)d_in[3];
    const float* b_off2 = (const float*)d_in[4];
    const float* w_def1 = (const float*)d_in[5];
    const float* w_def2 = (const float*)d_in[6];
    const float* gamma1 = (const float*)d_in[7];
    const float* beta1  = (const float*)d_in[8];
    const float* gamma2 = (const float*)d_in[9];
    const float* beta2  = (const float*)d_in[10];
    float* out = (float*)d_out;

    cudaFuncSetAttribute(mma_gemm_kernel, cudaFuncAttributeMaxDynamicSharedMemorySize,
                         GSMEM);

    dim3 conv_grid(4, 4, BB * 4);
    dim3 gath_grid(HW / 256, KK, BB * 4);
    dim3 gemm_grid(HW / 128, BB);
    dim3 gn_grid(BB * G, 4);
    int init_blocks = (BB * OC_OFF * HW + 255) / 256;
    int wprep_blocks = (2 * C * CK + 255) / 256;  // covers g_offset init range too

    // ---- stage 1 (stage-1 offset init folded into wprep) ----
    wprep_kernel<<<wprep_blocks, 256>>>(w_def1, w_def2, b_off1);
    offset_conv_kernel<<<conv_grid, 256>>>(x, w_off1, 0);
    gather_kernel<<<gath_grid, 256>>>(x, 0);
    mma_gemm_kernel<<<gemm_grid, 512, GSMEM>>>(0);
    gn_kernel<<<gn_grid, 256>>>(gamma1, beta1, nullptr, nullptr, 1);

    // ---- stage 2 ----
    init_offset_kernel<<<init_blocks, 256>>>(b_off2);
    offset_conv_kernel<<<conv_grid, 256>>>(nullptr, w_off2, 1);
    gather_kernel<<<gath_grid, 256>>>(nullptr, 1);
    mma_gemm_kernel<<<gemm_grid, 512, GSMEM>>>(1);
    gn_kernel<<<gn_grid, 256>>>(gamma2, beta2, x, out, 0);
}

// round 16
// speedup vs baseline: 1.0702x; 1.0702x over previous
#include <cuda_runtime.h>
#include <cuda_fp16.h>
#include <cstdint>

#define BB 4
#define C 256
#define H 64
#define W 64
#define HW 4096
#define G 32
#define KK 9
#define OC_OFF 18
#define CK 2304  /* C * KK */
#define NCHUNK 36 /* CK / 64 */

// ---------------- device scratch (static, no runtime allocation) -------------
__device__ float g_offset[BB * OC_OFF * HW];                        // 1.18 MB
// A blocks: [b][ptile 32][chunk 36] of 16 KB (128 pixels x 128 B, swizzled)
__device__ __align__(16) char g_val2[(size_t)BB * 32 * NCHUNK * 16384];  // 75.5 MB
// B blocks: [stage][chunk 36] of 32 KB (256 oc x 128 B, swizzled)
__device__ __align__(16) char g_wb[2 * NCHUNK * 32768];             // 2.36 MB
__device__ float g_tmp[(size_t)BB * C * HW];                        // 16.8 MB
__device__ float g_stat[2 * BB * G * 2];                            // per-stage sums

// ---------------- helpers ----------------------------------------------------
__device__ __forceinline__ uint32_t smem_u32(const void* p) {
    uint32_t a;
    asm("{ .reg .u64 t; cvta.to.shared.u64 t, %1; cvt.u32.u64 %0, t; }"
        : "=r"(a) : "l"(p));
    return a;
}
__device__ __forceinline__ uint32_t swz(uint32_t o) { return o ^ ((o >> 3) & 0x70); }

__device__ __forceinline__ void bulk_cp(uint32_t sdst, const void* gsrc,
                                        uint32_t bytes, uint32_t mbar) {
    asm volatile(
        "cp.async.bulk.shared::cluster.global.mbarrier::complete_tx::bytes "
        "[%0], [%1], %2, [%3];"
        :: "r"(sdst), "l"(gsrc), "r"(bytes), "r"(mbar) : "memory");
}
__device__ __forceinline__ void mbar_init(uint32_t a, uint32_t cnt) {
    asm volatile("mbarrier.init.shared.b64 [%0], %1;" :: "r"(a), "r"(cnt) : "memory");
}
__device__ __forceinline__ void mbar_expect(uint32_t a, uint32_t bytes) {
    asm volatile("mbarrier.arrive.expect_tx.shared.b64 _, [%0], %1;"
                 :: "r"(a), "r"(bytes) : "memory");
}
__device__ __forceinline__ void mbar_wait(uint32_t a, uint32_t parity) {
    asm volatile(
        "{\n\t.reg .pred P1;\n\t"
        "WL%=:\n\t"
        "mbarrier.try_wait.parity.acquire.cta.shared::cta.b64 P1, [%0], %1, 0x989680;\n\t"
        "@P1 bra.uni WD%=;\n\t"
        "bra.uni WL%=;\n\t"
        "WD%=:\n\t}" :: "r"(a), "r"(parity) : "memory");
}

#define MMA_F16(d, a, bfr)                                                   \
    asm volatile(                                                            \
        "mma.sync.aligned.m16n8k16.row.col.f32.f16.f16.f32 "                 \
        "{%0,%1,%2,%3}, {%4,%5,%6,%7}, {%8,%9}, {%0,%1,%2,%3};"              \
        : "+f"((d)[0]), "+f"((d)[1]), "+f"((d)[2]), "+f"((d)[3])             \
        : "r"((a)[0]), "r"((a)[1]), "r"((a)[2]), "r"((a)[3]),                \
          "r"((bfr)[0]), "r"((bfr)[1]))

#define LDSM_X4(fr, addr)                                                    \
    asm volatile("ldmatrix.sync.aligned.m8n8.x4.shared.b16 "                 \
                 "{%0,%1,%2,%3}, [%4];"                                      \
                 : "=r"((fr)[0]), "=r"((fr)[1]), "=r"((fr)[2]), "=r"((fr)[3])\
                 : "r"(addr))

// ---------------- weight reorder + stage-1 offset init + stat clear ----------
__global__ void wprep_kernel(const float* __restrict__ w1, const float* __restrict__ w2,
                             const float* __restrict__ bias1) {
    int i = blockIdx.x * 256 + threadIdx.x;
    if (i < 2 * BB * G * 2) g_stat[i] = 0.f;
    if (i < BB * OC_OFF * HW) {
        int oc = (i / HW) % OC_OFF;
        g_offset[i] = bias1[oc];
    }
    if (i >= 2 * C * CK) return;
    int s = i / (C * CK);
    int rem = i - s * (C * CK);
    int oc = rem / CK;
    int r = rem - oc * CK;
    int k = r >> 8;
    int cin = r & 255;
    const float* w = s ? w2 : w1;
    __half hv = __float2half(w[(size_t)oc * CK + cin * 9 + k]);
    int chunk = r >> 6;
    uint32_t o = (uint32_t)oc * 128 + (uint32_t)(r & 63) * 2;
    *reinterpret_cast<unsigned short*>(
        g_wb + (((size_t)s * NCHUNK + chunk) << 15) + swz(o)) =
        __half_as_ushort(hv);
}

// ---------------- init offset buffer with bias (stage 2) ---------------------
__global__ void init_offset_kernel(const float* __restrict__ bias) {
    int i = blockIdx.x * 256 + threadIdx.x;
    if (i < BB * OC_OFF * HW) {
        int oc = (i / HW) % OC_OFF;
        g_offset[i] = bias[oc];
    }
}

// ---------------- offset conv3x3: C in -> 18 out, pad 1 ----------------------
// If gamma != nullptr, input = relu(gn1(g_tmp)) applied inline via smem table.
#define CIN_CHUNK 64
__global__ __launch_bounds__(256) void offset_conv_kernel(
    const float* __restrict__ xin, const float* __restrict__ woff,
    const float* __restrict__ gamma, const float* __restrict__ beta) {
    __shared__ __align__(16) float ws[CIN_CHUNK * 9 * 20];
    __shared__ float xs[2][18 * 18];
    __shared__ float s_gm[CIN_CHUNK], s_bt[CIN_CHUNK];

    int tid = threadIdx.x;
    int bz = blockIdx.z;
    int b = bz >> 2;
    int chunk = bz & 3;
    int cin0 = chunk * CIN_CHUNK;

    if (gamma) {
        if (tid < CIN_CHUNK) {
            int c = cin0 + tid;
            int bg = b * G + (c >> 3);
            float inv_n = 1.f / 32768.f;
            float mu = g_stat[bg * 2] * inv_n;
            float rstd = rsqrtf(g_stat[bg * 2 + 1] * inv_n - mu * mu + 1e-5f);
            float gm = gamma[c] * rstd;
            s_gm[tid] = gm;
            s_bt[tid] = beta[c] - mu * gm;
        }
    } else if (tid < CIN_CHUNK) {
        s_gm[tid] = 1.f;
        s_bt[tid] = 0.f;
    }

    for (int idx = tid; idx < CIN_CHUNK * 9 * 18; idx += 256) {
        int cl = idx / 162;
        int rem = idx - cl * 162;
        int k = rem / 18;
        int oc = rem - k * 18;
        ws[(cl * 9 + k) * 20 + oc] =
            woff[(size_t)oc * (C * 9) + (size_t)(cin0 + cl) * 9 + k];
    }

    int ty = tid >> 4, tx = tid & 15;
    int py0 = blockIdx.y * 16, px0 = blockIdx.x * 16;

    float acc[18];
#pragma unroll
    for (int i = 0; i < 18; i++) acc[i] = 0.f;

    const float* src = gamma ? g_tmp : xin;
    const float* xb = src + ((size_t)b * C + cin0) * HW;
    bool do_act = (gamma != nullptr);

    int hidx0 = tid;
    int hidx1 = tid + 256;
    int hr0 = hidx0 / 18, hc0 = hidx0 - hr0 * 18;
    int hr1 = hidx1 / 18, hc1 = hidx1 - hr1 * 18;
    int gy0 = py0 - 1 + hr0, gx0 = px0 - 1 + hc0;
    int gy1 = py0 - 1 + hr1, gx1 = px0 - 1 + hc1;
    bool v0 = (gy0 >= 0 && gy0 < H && gx0 >= 0 && gx0 < W);
    bool v1 = (hidx1 < 324) && (gy1 >= 0 && gy1 < H && gx1 >= 0 && gx1 < W);
    int go0 = gy0 * W + gx0, go1 = gy1 * W + gx1;

    __syncthreads();  // s_gm/s_bt ready before use below

    {
        const float* xc = xb;
        float a0 = v0 ? xc[go0] : 0.f;
        float a1 = v1 ? xc[go1] : 0.f;
        if (do_act) {
            a0 = v0 ? fmaxf(a0 * s_gm[0] + s_bt[0], 0.f) : 0.f;
            a1 = v1 ? fmaxf(a1 * s_gm[0] + s_bt[0], 0.f) : 0.f;
        }
        xs[0][hidx0] = a0;
        if (hidx1 < 324) xs[0][hidx1] = a1;
    }
    __syncthreads();

#pragma unroll 1
    for (int cl = 0; cl < CIN_CHUNK; cl++) {
        int cur = cl & 1;
        if (cl + 1 < CIN_CHUNK) {
            const float* xn = xb + (size_t)(cl + 1) * HW;
            float gmn = s_gm[cl + 1], btn = s_bt[cl + 1];
            float a0 = v0 ? __ldg(xn + go0) : 0.f;
            float a1 = v1 ? __ldg(xn + go1) : 0.f;
            if (do_act) {
                a0 = v0 ? fmaxf(a0 * gmn + btn, 0.f) : 0.f;
                a1 = v1 ? fmaxf(a1 * gmn + btn, 0.f) : 0.f;
            }
            xs[cur ^ 1][hidx0] = a0;
            if (hidx1 < 324) xs[cur ^ 1][hidx1] = a1;
        }

        float xv[9];
#pragma unroll
        for (int ky = 0; ky < 3; ky++)
#pragma unroll
            for (int kx = 0; kx < 3; kx++)
                xv[ky * 3 + kx] = xs[cur][(ty + ky) * 18 + (tx + kx)];

#pragma unroll
        for (int k = 0; k < 9; k++) {
            const float* wr = &ws[(cl * 9 + k) * 20];
            float xk = xv[k];
#pragma unroll
            for (int oc = 0; oc < 18; oc++) acc[oc] += xk * wr[oc];
        }
        __syncthreads();
    }

    int p = (py0 + ty) * W + (px0 + tx);
    float* ob = g_offset + (size_t)b * OC_OFF * HW + p;
#pragma unroll
    for (int oc = 0; oc < 18; oc++) atomicAdd(ob + (size_t)oc * HW, acc[oc]);
}

// ---------------- bilinear gather -> swizzled A blocks (fp16) ----------------
// If gamma != nullptr, samples relu(gn1(g_tmp)) applied inline.
__global__ __launch_bounds__(256) void gather_kernel(
    const float* __restrict__ xin, const float* __restrict__ gamma,
    const float* __restrict__ beta) {
    __shared__ __align__(16) char sv[256 * 128];  // 32 KB = 2 ptile blocks
    __shared__ float s_gm[64], s_bt[64];
    int tid = threadIdx.x;
    int p = blockIdx.x * 256 + tid;
    int k = blockIdx.y;
    int b = blockIdx.z >> 2;
    int cin0 = (blockIdx.z & 3) * 64;
    int h = p >> 6, w = p & 63;

    bool do_act = (gamma != nullptr);
    if (tid < 64) {
        if (do_act) {
            int c = cin0 + tid;
            int bg = b * G + (c >> 3);
            float inv_n = 1.f / 32768.f;
            float mu = g_stat[bg * 2] * inv_n;
            float rstd = rsqrtf(g_stat[bg * 2 + 1] * inv_n - mu * mu + 1e-5f);
            float gm = gamma[c] * rstd;
            s_gm[tid] = gm;
            s_bt[tid] = beta[c] - mu * gm;
        } else {
            s_gm[tid] = 1.f;
            s_bt[tid] = 0.f;
        }
    }

    const float* off = g_offset + ((size_t)b * OC_OFF + 2 * k) * HW + p;
    float dy = off[0];
    float dx = off[HW];
    int ky = k / 3, kx = k - ky * 3;

    float py = dy + (float)(h - 1 + ky);
    float px = dx + (float)(w - 1 + kx);
    float fy = floorf(py), fx = floorf(px);
    int iy0 = (int)fy, ix0 = (int)fx;
    float ly = py - fy, lx = px - fx;

    float vy0 = (iy0 >= 0 && iy0 < H) ? 1.f : 0.f;
    float vy1 = (iy0 + 1 >= 0 && iy0 + 1 < H) ? 1.f : 0.f;
    float vx0 = (ix0 >= 0 && ix0 < W) ? 1.f : 0.f;
    float vx1 = (ix0 + 1 >= 0 && ix0 + 1 < W) ? 1.f : 0.f;

    float w00 = (1.f - ly) * (1.f - lx) * vy0 * vx0;
    float w01 = (1.f - ly) * lx * vy0 * vx1;
    float w10 = ly * (1.f - lx) * vy1 * vx0;
    float w11 = ly * lx * vy1 * vx1;

    int cy0 = min(max(iy0, 0), H - 1);
    int cy1 = min(max(iy0 + 1, 0), H - 1);
    int cx0 = min(max(ix0, 0), W - 1);
    int cx1 = min(max(ix0 + 1, 0), W - 1);
    int i00 = cy0 * W + cx0, i01 = cy0 * W + cx1;
    int i10 = cy1 * W + cx0, i11 = cy1 * W + cx1;

    const float* src = do_act ? g_tmp : xin;
    const float* xb = src + (size_t)b * C * HW;
    __syncthreads();  // s_gm/s_bt ready

#pragma unroll 1
    for (int g = 0; g < 4; g++) {
        int c0 = cin0 + g * 16;
        const float* xc = xb + (size_t)c0 * HW;
        float v00[16], v01[16], v10[16], v11[16];
#pragma unroll
        for (int j = 0; j < 16; j++) v00[j] = __ldg(xc + (size_t)j * HW + i00);
#pragma unroll
        for (int j = 0; j < 16; j++) v01[j] = __ldg(xc + (size_t)j * HW + i01);
#pragma unroll
        for (int j = 0; j < 16; j++) v10[j] = __ldg(xc + (size_t)j * HW + i10);
#pragma unroll
        for (int j = 0; j < 16; j++) v11[j] = __ldg(xc + (size_t)j * HW + i11);

        __align__(16) __half hb[16];
#pragma unroll
        for (int j = 0; j < 16; j++) {
            float a = v00[j], bq = v01[j], cq = v10[j], d = v11[j];
            if (do_act) {
                float gm = s_gm[g * 16 + j], bt = s_bt[g * 16 + j];
                a = fmaxf(a * gm + bt, 0.f);
                bq = fmaxf(bq * gm + bt, 0.f);
                cq = fmaxf(cq * gm + bt, 0.f);
                d = fmaxf(d * gm + bt, 0.f);
            }
            float s = w00 * a + w01 * bq + w10 * cq + w11 * d;
            hb[j] = __float2half(s);
        }
        uint32_t o0 = (uint32_t)tid * 128 + g * 32;
        uint32_t o1 = o0 + 16;
        *reinterpret_cast<uint4*>(sv + swz(o0)) = *reinterpret_cast<const uint4*>(hb);
        *reinterpret_cast<uint4*>(sv + swz(o1)) =
            *reinterpret_cast<const uint4*>(hb + 8);
    }
    __syncthreads();

    int chunk = k * 4 + (blockIdx.z & 3);
#pragma unroll
    for (int t = 0; t < 8; t++) {
        uint32_t idx = ((uint32_t)tid + t * 256) * 16;
        int pt = blockIdx.x * 2 + (idx >> 14);
        size_t base = (((size_t)b * 32 + pt) * NCHUNK + chunk) << 14;
        *reinterpret_cast<uint4*>(g_val2 + base + (idx & 16383)) =
            *reinterpret_cast<const uint4*>(sv + idx);
    }
}

// ---------------- HMMA GEMM with cp.async.bulk chunk loads (R14) -------------
#define STG 49152
#define GSMEM (3 * STG) /* 147456 */

__global__ __launch_bounds__(512, 1) void mma_gemm_kernel(int stage) {
    extern __shared__ __align__(16) char smem[];
    __shared__ __align__(8) unsigned long long mb8[3];
    uint32_t sb = smem_u32(smem);
    uint32_t mb = smem_u32(mb8);
    int tid = threadIdx.x;
    int wid = tid >> 5, lane = tid & 31;
    int b = blockIdx.y;
    int ptile = blockIdx.x;
    int p0 = ptile * 128;

    const char* Ag = g_val2 + (((size_t)b * 32 + ptile) * NCHUNK << 14);
    const char* Bg = g_wb + ((size_t)stage * NCHUNK << 15);

    if (tid == 0) {
#pragma unroll
        for (int s = 0; s < 3; s++) mbar_init(mb + 8 * s, 1);
    }
    __syncthreads();

    if (tid == 0) {
#pragma unroll
        for (int s = 0; s < 3; s++) {
            mbar_expect(mb + 8 * s, 49152);
            bulk_cp(sb + s * STG, Ag + ((size_t)s << 14), 16384, mb + 8 * s);
            bulk_cp(sb + s * STG + 16384, Bg + ((size_t)s << 15), 32768, mb + 8 * s);
        }
    }

    int mwarp = wid >> 3, nwarp = wid & 7;
    uint32_t arow_off[4];
#pragma unroll
    for (int mt = 0; mt < 4; mt++)
        arow_off[mt] = (uint32_t)(mwarp * 64 + mt * 16 + (lane & 15)) * 128;
    uint32_t acol = (lane >> 4) * 16;
    uint32_t brow_off[2];
#pragma unroll
    for (int ntp = 0; ntp < 2; ntp++)
        brow_off[ntp] =
            (uint32_t)(nwarp * 32 + ntp * 16 + (lane >> 4) * 8 + (lane & 7)) * 128;
    uint32_t bcol = ((lane >> 3) & 1) * 16;

    float acc[4][4][4];
#pragma unroll
    for (int i = 0; i < 4; i++)
#pragma unroll
        for (int j = 0; j < 4; j++)
#pragma unroll
            for (int q = 0; q < 4; q++) acc[i][j][q] = 0.f;

#pragma unroll 1
    for (int i = 0; i < NCHUNK; i++) {
        int buf = i % 3;
        mbar_wait(mb + 8 * buf, (i / 3) & 1);

        uint32_t cb = sb + (uint32_t)buf * STG;
#pragma unroll
        for (int kk = 0; kk < 4; kk++) {
            uint32_t koff = (uint32_t)kk * 32;
            uint32_t ah[4][4], bb[2][4];
#pragma unroll
            for (int mt = 0; mt < 4; mt++)
                LDSM_X4(ah[mt], cb + swz(arow_off[mt] + acol + koff));
#pragma unroll
            for (int ntp = 0; ntp < 2; ntp++)
                LDSM_X4(bb[ntp], cb + 16384 + swz(brow_off[ntp] + bcol + koff));
#pragma unroll
            for (int mt = 0; mt < 4; mt++)
#pragma unroll
                for (int nt = 0; nt < 4; nt++)
                    MMA_F16(acc[mt][nt], ah[mt], &bb[nt >> 1][(nt & 1) * 2]);
        }
        __syncthreads();

        if (tid == 0 && i + 3 < NCHUNK) {
            int nc = i + 3;
            mbar_expect(mb + 8 * buf, 49152);
            bulk_cp(cb, Ag + ((size_t)nc << 14), 16384, mb + 8 * buf);
            bulk_cp(cb + 16384, Bg + ((size_t)nc << 15), 32768, mb + 8 * buf);
        }
    }

    // ---------------- epilogue: two passes of 128 oc via smem transpose ------
    float* sf = reinterpret_cast<float*>(smem);
    float* stat = g_stat + stage * (BB * G * 2);
    int rl = lane >> 2;
    int cl2 = (lane & 3) * 2;
#pragma unroll 1
    for (int q = 0; q < 2; q++) {
        if ((nwarp >> 2) == q) {
#pragma unroll
            for (int mt = 0; mt < 4; mt++) {
#pragma unroll
                for (int nt = 0; nt < 4; nt++) {
                    int m = mwarp * 64 + mt * 16 + rl;
                    int n = (nwarp & 3) * 32 + nt * 8 + cl2;
                    sf[n * 132 + m] = acc[mt][nt][0];
                    sf[(n + 1) * 132 + m] = acc[mt][nt][1];
                    sf[n * 132 + m + 8] = acc[mt][nt][2];
                    sf[(n + 1) * 132 + m + 8] = acc[mt][nt][3];
                }
            }
        }
        __syncthreads();

#pragma unroll
        for (int t = 0; t < 8; t++) {
            int idx = tid + t * 512;
            int n = idx >> 5;
            int ms = (idx & 31) * 4;
            float4 v = *reinterpret_cast<const float4*>(sf + n * 132 + ms);
            int oc = q * 128 + n;
            *reinterpret_cast<float4*>(g_tmp + ((size_t)b * C + oc) * HW + p0 + ms) = v;

            float s1 = v.x + v.y + v.z + v.w;
            float s2 = v.x * v.x + v.y * v.y + v.z * v.z + v.w * v.w;
#pragma unroll
            for (int o = 16; o > 0; o >>= 1) {
                s1 += __shfl_xor_sync(0xffffffffu, s1, o);
                s2 += __shfl_xor_sync(0xffffffffu, s2, o);
            }
            if (lane == 0) {
                int bg = b * G + (oc >> 3);
                atomicAdd(&stat[bg * 2], s1);
                atomicAdd(&stat[bg * 2 + 1], s2);
            }
        }
        __syncthreads();
    }
}

// ---------------- final GroupNorm apply + residual + ReLU --------------------
__global__ __launch_bounds__(256) void gn_kernel(const float* __restrict__ gamma,
                                                 const float* __restrict__ beta,
                                                 const float* __restrict__ residual,
                                                 float* __restrict__ outp) {
    int bg = blockIdx.x;
    int b = bg >> 5;
    int g = bg & 31;
    int quarter = blockIdx.y;
    size_t chan_off = ((size_t)b * C + (size_t)g * 8 + (size_t)quarter * 2) * HW;
    const float4* in4 = reinterpret_cast<const float4*>(g_tmp + chan_off);
    const float* stat = g_stat + (BB * G * 2);  // stage-2 stats

    __shared__ float stats[2];
    if (threadIdx.x == 0) {
        float inv_n = 1.f / 32768.f;
        float mu = stat[bg * 2] * inv_n;
        stats[0] = mu;
        stats[1] = rsqrtf(stat[bg * 2 + 1] * inv_n - mu * mu + 1e-5f);
    }
    __syncthreads();
    float mu = stats[0], rstd = stats[1];

    int tid = threadIdx.x;
    float4* out4 = reinterpret_cast<float4*>(outp + chan_off);
    const float4* res4 = reinterpret_cast<const float4*>(residual + chan_off);

    for (int i = tid; i < 2 * HW / 4; i += 256) {
        int c = g * 8 + quarter * 2 + (i >> 10);
        float gm = gamma[c] * rstd;
        float bt = beta[c] - mu * gm;
        float4 v = in4[i];
        float4 r = res4[i];
        v.x = fmaxf(v.x * gm + bt + r.x, 0.f);
        v.y = fmaxf(v.y * gm + bt + r.y, 0.f);
        v.z = fmaxf(v.z * gm + bt + r.z, 0.f);
        v.w = fmaxf(v.w * gm + bt + r.w, 0.f);
        out4[i] = v;
    }
}

// ---------------- launcher ---------------------------------------------------
extern "C" void kernel_launch(void* const* d_in, const int* in_sizes, int n_in,
                              void* d_out, int out_size) {
    const float* x      = (const float*)d_in[0];
    const float* w_off1 = (const float*)d_in[1];
    const float* b_off1 = (const float*)d_in[2];
    const float* w_off2 = (const float*)d_in[3];
    const float* b_off2 = (const float*)d_in[4];
    const float* w_def1 = (const float*)d_in[5];
    const float* w_def2 = (const float*)d_in[6];
    const float* gamma1 = (const float*)d_in[7];
    const float* beta1  = (const float*)d_in[8];
    const float* gamma2 = (const float*)d_in[9];
    const float* beta2  = (const float*)d_in[10];
    float* out = (float*)d_out;

    cudaFuncSetAttribute(mma_gemm_kernel, cudaFuncAttributeMaxDynamicSharedMemorySize,
                         GSMEM);

    dim3 conv_grid(4, 4, BB * 4);
    dim3 gath_grid(HW / 256, KK, BB * 4);
    dim3 gemm_grid(HW / 128, BB);
    dim3 gn_grid(BB * G, 4);
    int init_blocks = (BB * OC_OFF * HW + 255) / 256;
    int wprep_blocks = (2 * C * CK + 255) / 256;  // covers g_offset + g_stat ranges

    // ---- stage 1 ----
    wprep_kernel<<<wprep_blocks, 256>>>(w_def1, w_def2, b_off1);
    offset_conv_kernel<<<conv_grid, 256>>>(x, w_off1, nullptr, nullptr);
    gather_kernel<<<gath_grid, 256>>>(x, nullptr, nullptr);
    mma_gemm_kernel<<<gemm_grid, 512, GSMEM>>>(0);

    // ---- stage 2 (gn1 fused into conv2 / gather2 loads) ----
    init_offset_kernel<<<init_blocks, 256>>>(b_off2);
    offset_conv_kernel<<<conv_grid, 256>>>(nullptr, w_off2, gamma1, beta1);
    gather_kernel<<<gath_grid, 256>>>(nullptr, gamma1, beta1);
    mma_gemm_kernel<<<gemm_grid, 512, GSMEM>>>(1);
    gn_kernel<<<gn_grid, 256>>>(gamma2, beta2, x, out);
}